// round 5
// baseline (speedup 1.0000x reference)
#include <cuda_runtime.h>
#include <math.h>

// x: [B=4, C=64, H=64, W=64, D=64] fp32
// out = x + irfftn(delta), delta = (gate-1)*rfftn(x) on corner [16,16,9]
#define NPLANES 16384   // B*C*H
#define GATE_DIM 2304   // 16*16*9
#define NCOL    144     // 16 ky * 9 kz

__device__ float2 g_Y[NPLANES * NCOL];     // 18.9 MB intermediate spectrum
__device__ float  g_planesum[NPLANES];
__device__ float  g_hid[64];               // hidden layer [b*16+j]
__device__ float  g_gate[4 * GATE_DIM];    // (sigmoid-1)/64^3

#define INV_N3 (1.0f / 262144.0f)

// Compile-time twiddles: TWC[t] = cos(2*pi*t/64), sin via index shift.
__device__ constexpr float TWC[64] = {
     1.00000000f,  0.99518473f,  0.98078528f,  0.95694034f,
     0.92387953f,  0.88192126f,  0.83146961f,  0.77301045f,
     0.70710678f,  0.63439328f,  0.55557023f,  0.47139674f,
     0.38268343f,  0.29028468f,  0.19509032f,  0.09801714f,
     0.00000000f, -0.09801714f, -0.19509032f, -0.29028468f,
    -0.38268343f, -0.47139674f, -0.55557023f, -0.63439328f,
    -0.70710678f, -0.77301045f, -0.83146961f, -0.88192126f,
    -0.92387953f, -0.95694034f, -0.98078528f, -0.99518473f,
    -1.00000000f, -0.99518473f, -0.98078528f, -0.95694034f,
    -0.92387953f, -0.88192126f, -0.83146961f, -0.77301045f,
    -0.70710678f, -0.63439328f, -0.55557023f, -0.47139674f,
    -0.38268343f, -0.29028468f, -0.19509032f, -0.09801714f,
     0.00000000f,  0.09801714f,  0.19509032f,  0.29028468f,
     0.38268343f,  0.47139674f,  0.55557023f,  0.63439328f,
     0.70710678f,  0.77301045f,  0.83146961f,  0.88192126f,
     0.92387953f,  0.95694034f,  0.98078528f,  0.99518473f
};
__device__ __forceinline__ constexpr float twc(int t) { return TWC[t & 63]; }
__device__ __forceinline__ constexpr float tws(int t) { return TWC[(t + 48) & 63]; }

// runtime twiddle table in smem: tw[t] = (cos, sin)
__device__ __forceinline__ void fill_tw(float2* tw, int tid) {
    if (tid < 64) {
        float s, c;
        sincospif((float)tid * (1.0f / 32.0f), &s, &c);
        tw[tid] = make_float2(c, s);
    }
}

// Folded z-DFT chunk: dp in [DP0, DP0+NDP), all 9 kz, compile-time twiddles.
template<int DP0, int NDP>
__device__ __forceinline__ void zchunk(const float* __restrict__ row,
                                       float* re, float* im) {
    #pragma unroll
    for (int i = 0; i < NDP; i++) {
        const int dp = DP0 + i;
        const float a = row[dp], b = row[64 - dp];
        const float e = a + b, o = a - b;
        re[0] += e;
        #pragma unroll
        for (int kz = 1; kz < 9; kz++) {
            re[kz] = fmaf(e, twc(kz * dp), re[kz]);
            im[kz] = fmaf(o, -tws(kz * dp), im[kz]);
        }
    }
}

// ---------------------------------------------------------------------------
// Kernel 1: per-plane (b,c,h): plane sum, z-DFT (const twiddles, chunked over
// dp with smem reduction), y-DFT split into 288 half-range tasks.
// ---------------------------------------------------------------------------
__global__ void __launch_bounds__(256) k_fwd(const float* __restrict__ x) {
    __shared__ __align__(16) float xs[64 * 65];   // [w][d] stride 65; later reused as Zs
    __shared__ float2 Zpart[4 * 64 * 9];          // [q][w][kz]
    __shared__ float2 Ypart[288];                 // y-DFT halves
    __shared__ float2 tw[64];
    __shared__ float  red[8];
    float2* Zs = (float2*)xs;                     // overlay (xs dead by then)

    const int plane = blockIdx.x;
    const int tid   = threadIdx.x;
    fill_tw(tw, tid);

    // Plane load (float4) + pooling sum
    const float4* xp4 = (const float4*)(x + (size_t)plane * 4096);
    float psum = 0.0f;
    #pragma unroll
    for (int k = 0; k < 4; k++) {
        const int i4 = k * 256 + tid;
        float4 v = xp4[i4];
        const int base = i4 * 4;
        float* dst = &xs[(base >> 6) * 65 + (base & 63)];
        dst[0] = v.x; dst[1] = v.y; dst[2] = v.z; dst[3] = v.w;
        psum += (v.x + v.y) + (v.z + v.w);
    }
    #pragma unroll
    for (int o = 16; o > 0; o >>= 1) psum += __shfl_down_sync(0xffffffffu, psum, o);
    if ((tid & 31) == 0) red[tid >> 5] = psum;
    __syncthreads();                               // xs + red ready
    if (tid == 0) {
        float s = 0.0f;
        #pragma unroll
        for (int i = 0; i < 8; i++) s += red[i];
        g_planesum[plane] = s;
    }

    // z-DFT: thread (w = tid&63, q = tid>>6): dp-chunk for all 9 kz
    {
        const int w = tid & 63;
        const int q = tid >> 6;
        float re[9], im[9];
        #pragma unroll
        for (int kz = 0; kz < 9; kz++) { re[kz] = 0.f; im[kz] = 0.f; }
        const float* row = &xs[w * 65];
        if (q == 0)      zchunk<1, 8>(row, re, im);
        else if (q == 1) zchunk<9, 8>(row, re, im);
        else if (q == 2) zchunk<17, 8>(row, re, im);
        else {
            zchunk<25, 7>(row, re, im);
            const float x0 = row[0], x32 = row[32];
            #pragma unroll
            for (int kz = 0; kz < 9; kz++)
                re[kz] += x0 + ((kz & 1) ? -x32 : x32);
        }
        float2* zp = &Zpart[(q * 64 + w) * 9];
        #pragma unroll
        for (int kz = 0; kz < 9; kz++) zp[kz] = make_float2(re[kz], im[kz]);
    }
    __syncthreads();

    // Combine 4 partials -> Zs[w][kz] (overlaid on xs)
    for (int j = tid; j < 576; j += 256) {
        const int ww = j / 9, kz = j - ww * 9;
        float2 a = Zpart[ww * 9 + kz];
        float2 b = Zpart[(64 + ww) * 9 + kz];
        float2 c = Zpart[(128 + ww) * 9 + kz];
        float2 d = Zpart[(192 + ww) * 9 + kz];
        Zs[ww * 9 + kz] = make_float2((a.x + b.x) + (c.x + d.x),
                                      (a.y + b.y) + (c.y + d.y));
    }
    __syncthreads();

    // y-DFT: 288 tasks; j<144 -> wp 1..16 (+edges), j>=144 -> wp 17..31
    for (int j = tid; j < 288; j += 256) {
        float re = 0.f, im = 0.f;
        if (j < 144) {
            const int ky = j / 9, kz = j - ky * 9;
            float2 z0 = Zs[kz], z32 = Zs[32 * 9 + kz];
            const float sg = (ky & 1) ? -1.0f : 1.0f;
            re = fmaf(sg, z32.x, z0.x);
            im = fmaf(sg, z32.y, z0.y);
            #pragma unroll
            for (int wp = 1; wp <= 16; wp++) {
                float2 za = Zs[wp * 9 + kz];
                float2 zb = Zs[(64 - wp) * 9 + kz];
                float sx = za.x + zb.x, dxx = za.x - zb.x;
                float sy = za.y + zb.y, dy  = za.y - zb.y;
                float2 t = tw[(ky * wp) & 63];
                re = fmaf(sx, t.x, re); re = fmaf(dy, t.y, re);
                im = fmaf(sy, t.x, im); im = fmaf(-dxx, t.y, im);
            }
        } else {
            const int m = j - 144;
            const int ky = m / 9, kz = m - ky * 9;
            #pragma unroll
            for (int wp = 17; wp <= 31; wp++) {
                float2 za = Zs[wp * 9 + kz];
                float2 zb = Zs[(64 - wp) * 9 + kz];
                float sx = za.x + zb.x, dxx = za.x - zb.x;
                float sy = za.y + zb.y, dy  = za.y - zb.y;
                float2 t = tw[(ky * wp) & 63];
                re = fmaf(sx, t.x, re); re = fmaf(dy, t.y, re);
                im = fmaf(sy, t.x, im); im = fmaf(-dxx, t.y, im);
            }
        }
        Ypart[j] = make_float2(re, im);
    }
    __syncthreads();
    if (tid < 144) {
        float2 a = Ypart[tid], b = Ypart[tid + 144];
        g_Y[(size_t)plane * NCOL + tid] = make_float2(a.x + b.x, a.y + b.y);
    }
}

// ---------------------------------------------------------------------------
// Kernel 2a: pooled -> hidden (1 block)
// ---------------------------------------------------------------------------
__global__ void __launch_bounds__(256) k_gates1(const float* __restrict__ w1,
                                                const float* __restrict__ b1) {
    __shared__ float pooled_s[256];
    const int tid = threadIdx.x;
    {
        float s = 0.0f;
        const float* ps = &g_planesum[tid * 64];
        #pragma unroll 8
        for (int h = 0; h < 64; h++) s += ps[h];
        pooled_s[tid] = s * INV_N3;
    }
    __syncthreads();
    if (tid < 64) {
        const int b = tid >> 4, j = tid & 15;
        float acc = b1[j];
        #pragma unroll 8
        for (int c = 0; c < 64; c++) acc = fmaf(pooled_s[b * 64 + c], w1[c * 16 + j], acc);
        g_hid[tid] = fmaxf(acc, 0.0f);
    }
}

// ---------------------------------------------------------------------------
// Kernel 2b: hidden -> gates (grid 36)
// ---------------------------------------------------------------------------
__global__ void __launch_bounds__(256) k_gates2(const float* __restrict__ w2,
                                                const float* __restrict__ b2) {
    const int j2 = blockIdx.x * 256 + threadIdx.x;   // 0..9215
    const int b = j2 / GATE_DIM, m = j2 - b * GATE_DIM;
    float acc = b2[m];
    #pragma unroll
    for (int j = 0; j < 16; j++) acc = fmaf(g_hid[b * 16 + j], w2[j * GATE_DIM + m], acc);
    float sig = 1.0f / (1.0f + expf(-acc));
    g_gate[j2] = (sig - 1.0f) * INV_N3;
}

// ---------------------------------------------------------------------------
// Kernel 3: per (bc, 36-mode chunk): folded x-DFT -> gate -> folded x-inverse
// ---------------------------------------------------------------------------
#define MCH 36
__global__ void __launch_bounds__(256) k_xstage() {
    __shared__ float2 Ys[64 * MCH];
    __shared__ float2 As[MCH * 17];
    __shared__ float2 tw[64];

    const int bx  = blockIdx.x;
    const int bc  = bx >> 2;
    const int b   = bc >> 6;
    const int m0  = (bx & 3) * MCH;
    const int tid = threadIdx.x;
    fill_tw(tw, tid);

    float2* Yg = &g_Y[(size_t)bc * 64 * NCOL];
    for (int j = tid; j < 64 * MCH; j += 256) {
        const int h = j / MCH, mL = j % MCH;
        Ys[j] = Yg[h * NCOL + m0 + mL];
    }
    __syncthreads();

    for (int j = tid; j < MCH * 16; j += 256) {
        const int kx = j / MCH;
        const int mL = j % MCH;
        const float sg = (kx & 1) ? -1.0f : 1.0f;
        float2 z0 = Ys[mL], z32 = Ys[32 * MCH + mL];
        float re = fmaf(sg, z32.x, z0.x);
        float im = fmaf(sg, z32.y, z0.y);
        #pragma unroll 31
        for (int hp = 1; hp <= 31; hp++) {
            float2 za = Ys[hp * MCH + mL];
            float2 zb = Ys[(64 - hp) * MCH + mL];
            float sx = za.x + zb.x, dxx = za.x - zb.x;
            float sy = za.y + zb.y, dy  = za.y - zb.y;
            float2 t = tw[(kx * hp) & 63];
            re = fmaf(sx, t.x, re); re = fmaf(dy, t.y, re);
            im = fmaf(sy, t.x, im); im = fmaf(-dxx, t.y, im);
        }
        float gate = g_gate[b * GATE_DIM + kx * NCOL + m0 + mL];
        As[mL * 17 + kx] = make_float2(re * gate, im * gate);
    }
    __syncthreads();

    for (int j = tid; j < 32 * MCH; j += 256) {
        const int hp = j / MCH;
        const int mL = j % MCH;
        float P = 0.f, Q = 0.f, R = 0.f, S = 0.f;
        #pragma unroll
        for (int kx = 0; kx < 16; kx++) {
            float2 A = As[mL * 17 + kx];
            float2 t = tw[(kx * hp) & 63];
            P = fmaf(A.x, t.x, P); Q = fmaf(A.y, t.y, Q);
            R = fmaf(A.y, t.x, R); S = fmaf(A.x, t.y, S);
        }
        if (hp == 0) {
            float P32 = 0.f, R32 = 0.f;
            #pragma unroll
            for (int kx = 0; kx < 16; kx++) {
                float2 A = As[mL * 17 + kx];
                float sg = (kx & 1) ? -1.0f : 1.0f;
                P32 = fmaf(A.x, sg, P32); R32 = fmaf(A.y, sg, R32);
            }
            Yg[m0 + mL]             = make_float2(P, R);
            Yg[32 * NCOL + m0 + mL] = make_float2(P32, R32);
        } else {
            Yg[hp * NCOL + m0 + mL]        = make_float2(P - Q, S + R);
            Yg[(64 - hp) * NCOL + m0 + mL] = make_float2(P + Q, R - S);
        }
    }
}

// ---------------------------------------------------------------------------
// Kernel 4: per-plane: y-inverse (vectorized Yrow), z-synthesis, out = x+delta
// ---------------------------------------------------------------------------
__global__ void __launch_bounds__(256, 5) k_inv(const float* __restrict__ x,
                                                float* __restrict__ out) {
    __shared__ __align__(16) float2 Yrow2[9 * 16];   // [kz][ky]
    __shared__ __align__(16) float2 B2s[64 * 10];    // padded rows (80B)
    __shared__ float2 tw[64];

    const int plane = blockIdx.x;
    const int tid   = threadIdx.x;
    fill_tw(tw, tid);
    if (tid < NCOL) {
        const int ky = tid / 9, kz = tid - ky * 9;
        Yrow2[kz * 16 + ky] = g_Y[(size_t)plane * NCOL + tid];
    }
    __syncthreads();

    // Folded y-inverse
    for (int j = tid; j < 297; j += 256) {
        if (j < 279) {
            const int wp = j / 9 + 1;
            const int kz = j - (wp - 1) * 9;
            const float4* yp = (const float4*)&Yrow2[kz * 16];
            float rc = 0.f, rs = 0.f, ic = 0.f, is_ = 0.f;
            #pragma unroll
            for (int kh = 0; kh < 8; kh++) {
                float4 v = yp[kh];                 // (re,im) for ky=2kh, 2kh+1
                float2 t0 = tw[((2 * kh) * wp) & 63];
                float2 t1 = tw[((2 * kh + 1) * wp) & 63];
                rc = fmaf(v.x, t0.x, rc); rs  = fmaf(v.y, t0.y, rs);
                ic = fmaf(v.y, t0.x, ic); is_ = fmaf(v.x, t0.y, is_);
                rc = fmaf(v.z, t1.x, rc); rs  = fmaf(v.w, t1.y, rs);
                ic = fmaf(v.w, t1.x, ic); is_ = fmaf(v.z, t1.y, is_);
            }
            B2s[wp * 10 + kz]        = make_float2(rc - rs, is_ + ic);
            B2s[(64 - wp) * 10 + kz] = make_float2(rc + rs, ic - is_);
        } else if (j < 288) {
            const int kz = j - 279;                // w = 0
            const float4* yp = (const float4*)&Yrow2[kz * 16];
            float re = 0.f, im = 0.f;
            #pragma unroll
            for (int kh = 0; kh < 8; kh++) { float4 v = yp[kh]; re += v.x + v.z; im += v.y + v.w; }
            B2s[kz] = make_float2(re, im);
        } else {
            const int kz = j - 288;                // w = 32
            const float4* yp = (const float4*)&Yrow2[kz * 16];
            float re = 0.f, im = 0.f;
            #pragma unroll
            for (int kh = 0; kh < 8; kh++) { float4 v = yp[kh]; re += v.x - v.z; im += v.y - v.w; }
            B2s[32 * 10 + kz] = make_float2(re, im);
        }
    }
    __syncthreads();

    // Folded z-synthesis: lane dp -> d = dp and d = 64-dp (dp=0 -> 0 and 32)
    const int dp = tid & 31;
    const int wg = tid >> 5;
    float cs[8], ss[8];
    #pragma unroll
    for (int kz = 1; kz <= 8; kz++) {
        float2 t = tw[(kz * dp) & 63];
        cs[kz - 1] = t.x; ss[kz - 1] = t.y;
    }
    const size_t base = (size_t)plane * 4096;
    const int d2 = (dp == 0) ? 32 : (64 - dp);
    #pragma unroll
    for (int k = 0; k < 8; k++) {
        const int w = wg * 8 + k;
        const float4* bp = (const float4*)&B2s[w * 10];
        float4 p0 = bp[0], p1 = bp[1], p2 = bp[2], p3 = bp[3];
        float2 p8 = B2s[w * 10 + 8];
        float Ac = 0.f, As2 = 0.f;
        Ac = fmaf(p0.z, cs[0], Ac); As2 = fmaf(p0.w, ss[0], As2);
        Ac = fmaf(p1.x, cs[1], Ac); As2 = fmaf(p1.y, ss[1], As2);
        Ac = fmaf(p1.z, cs[2], Ac); As2 = fmaf(p1.w, ss[2], As2);
        Ac = fmaf(p2.x, cs[3], Ac); As2 = fmaf(p2.y, ss[3], As2);
        Ac = fmaf(p2.z, cs[4], Ac); As2 = fmaf(p2.w, ss[4], As2);
        Ac = fmaf(p3.x, cs[5], Ac); As2 = fmaf(p3.y, ss[5], As2);
        Ac = fmaf(p3.z, cs[6], Ac); As2 = fmaf(p3.w, ss[6], As2);
        Ac = fmaf(p8.x, cs[7], Ac); As2 = fmaf(p8.y, ss[7], As2);
        const float b0 = p0.x;
        float v1 = fmaf(2.0f, Ac - As2, b0);
        float v2;
        if (dp == 0) {
            float A32 = (((p1.x - p0.z) + (p2.x - p1.z)) +
                         ((p3.x - p2.z) + (p8.x - p3.z)));
            v2 = fmaf(2.0f, A32, b0);
        } else {
            v2 = fmaf(2.0f, Ac + As2, b0);
        }
        const size_t i1 = base + (size_t)w * 64 + dp;
        const size_t i2 = base + (size_t)w * 64 + d2;
        out[i1] = x[i1] + v1;
        out[i2] = x[i2] + v2;
    }
}

// ---------------------------------------------------------------------------
extern "C" void kernel_launch(void* const* d_in, const int* in_sizes, int n_in,
                              void* d_out, int out_size) {
    const float* x  = (const float*)d_in[0];
    const float* w1 = (const float*)d_in[1];
    const float* b1 = (const float*)d_in[2];
    const float* w2 = (const float*)d_in[3];
    const float* b2 = (const float*)d_in[4];
    float* out = (float*)d_out;

    k_fwd<<<NPLANES, 256>>>(x);
    k_gates1<<<1, 256>>>(w1, b1);
    k_gates2<<<36, 256>>>(w2, b2);
    k_xstage<<<1024, 256>>>();
    k_inv<<<NPLANES, 256>>>(x, out);
}